// round 12
// baseline (speedup 1.0000x reference)
#include <cuda_runtime.h>
#include <cstdint>

#define HW   16384      // 128*128
#define NCH  256
#define NB   8
#define NPIX 131072

typedef unsigned int u32;

__device__ __forceinline__ float sig1(float x) {
    return __fdividef(1.f, 1.f + __expf(-x));
}
__device__ __forceinline__ u32 tf32_rna(float x) {
    u32 r; asm("cvt.rna.tf32.f32 %0, %1;" : "=r"(r) : "f"(x)); return r;
}

// 24 partial dot products (22 used, 2 pad), layout [o][pixel]
__device__ float g_scratch[24 * NPIX];

// Output offsets (tuple flattened: xh_u_new, xh_l_new, att_u, att_l)
#define OUT_XHL  1310720
#define OUT_ATTU 2621440
#define OUT_ATTL 2752512

// =========================================================================
// Kernel 1: [131072 x 256] @ [256 x 24] GEMM via mma.sync m16n8k8 TF32,
// 3-term hi/lo split for fp32-grade accuracy.
// Each warp: 16 pixels, full K=256 (32 k8 chunks), 3 n8 tiles.
// =========================================================================
__global__ __launch_bounds__(256) void k1_main(
    const float* __restrict__ h_fea,
    const float* __restrict__ pdp_w1,
    const float* __restrict__ dU_aw,
    const float* __restrict__ dL_aw)
{
    // B fragment table: [k8chunk*3+nt][64 positions][hi,lo]  = 12288 floats, 48 KB
    __shared__ float sb[12288];
    const int tid = threadIdx.x;

    for (int idx = tid; idx < 6144; idx += 256) {
        int chunk = idx >> 6;            // k8*3 + nt
        int pos   = idx & 63;
        int k8 = chunk / 3, nt = chunk - 3 * k8;
        int k = k8 * 8 + (pos >> 3);
        int n = nt * 8 + (pos & 7);
        float w = 0.f;
        if (n < 20)       w = pdp_w1[n * 276 + k];
        else if (n == 20) w = dU_aw[k];
        else if (n == 21) w = dL_aw[k];
        float hi = __uint_as_float(tf32_rna(w));
        float lo = __uint_as_float(tf32_rna(w - hi));
        sb[idx * 2]     = hi;
        sb[idx * 2 + 1] = lo;
    }
    __syncthreads();

    const int wid = tid >> 5, l = tid & 31;
    const int gw  = blockIdx.x * 8 + wid;     // 8192 warps
    const int P0  = gw * 16;                  // 16 px per warp
    const int nim = P0 >> 14;
    const int pp  = P0 & (HW - 1);
    // lane-fixed A pointer: channel (l&3), pixel (l>>2)
    const float* ap = h_fea + nim * (NCH * HW) + (l & 3) * HW + pp + (l >> 2);
    const int pos0 = ((l & 3) * 8 + (l >> 2)) * 2;   // B frag float offset

    float c0[4] = {0.f, 0.f, 0.f, 0.f};
    float c1[4] = {0.f, 0.f, 0.f, 0.f};
    float c2[4] = {0.f, 0.f, 0.f, 0.f};

#define MMA(C, A0, A1, A2, A3, B0, B1)                                        \
    asm("mma.sync.aligned.m16n8k8.row.col.f32.tf32.tf32.f32 "                 \
        "{%0,%1,%2,%3},{%4,%5,%6,%7},{%8,%9},{%0,%1,%2,%3};"                  \
        : "+f"(C[0]), "+f"(C[1]), "+f"(C[2]), "+f"(C[3])                      \
        : "r"(A0), "r"(A1), "r"(A2), "r"(A3), "r"(B0), "r"(B1));

#pragma unroll 4
    for (int k8 = 0; k8 < 32; k8++) {
        const float* a8 = ap + k8 * 8 * HW;
        float f0 = a8[0];
        float f1 = a8[8];
        float f2 = a8[4 * HW];
        float f3 = a8[4 * HW + 8];

        u32 ah0 = tf32_rna(f0), ah1 = tf32_rna(f1);
        u32 ah2 = tf32_rna(f2), ah3 = tf32_rna(f3);
        u32 al0 = tf32_rna(f0 - __uint_as_float(ah0));
        u32 al1 = tf32_rna(f1 - __uint_as_float(ah1));
        u32 al2 = tf32_rna(f2 - __uint_as_float(ah2));
        u32 al3 = tf32_rna(f3 - __uint_as_float(ah3));

        const float* bb = &sb[k8 * 3 * 128];
#pragma unroll
        for (int nt = 0; nt < 3; nt++) {
            float2 p0 = *reinterpret_cast<const float2*>(bb + nt * 128 + pos0);
            float2 p1 = *reinterpret_cast<const float2*>(bb + nt * 128 + pos0 + 64);
            u32 bh0 = __float_as_uint(p0.x), bh1 = __float_as_uint(p1.x);
            u32 bl0 = __float_as_uint(p0.y), bl1 = __float_as_uint(p1.y);
            float* C = (nt == 0) ? c0 : (nt == 1) ? c1 : c2;
            MMA(C, ah0, ah1, ah2, ah3, bh0, bh1)      // hi*hi
            MMA(C, al0, al1, al2, al3, bh0, bh1)      // lo*hi
            MMA(C, ah0, ah1, ah2, ah3, bl0, bl1)      // hi*lo
        }
    }
#undef MMA

    // store: c0/c1 -> rows l>>2, c2/c3 -> rows (l>>2)+8; cols (l&3)*2, +1
    const int px = P0 + (l >> 2);
#pragma unroll
    for (int nt = 0; nt < 3; nt++) {
        const float* C = (nt == 0) ? c0 : (nt == 1) ? c1 : c2;
        int o0 = nt * 8 + (l & 3) * 2;
        g_scratch[o0 * NPIX + px]           = C[0];
        g_scratch[(o0 + 1) * NPIX + px]     = C[1];
        g_scratch[o0 * NPIX + px + 8]       = C[2];
        g_scratch[(o0 + 1) * NPIX + px + 8] = C[3];
    }
}

// =========================================================================
// Kernel 2: tails + graph logic — SCALAR, 1 pixel/thread. (R4-identical)
// =========================================================================
#define SB 440
#define O_W2    0
#define O_ATTW  200
#define O_ATTB  220
#define O_CUAW  222
#define O_CUAB  262
#define O_CUW   266
#define O_CLAW  466
#define O_CLAB  486
#define O_CLW   488
#define O_DUB   688
#define O_DUW   689
#define O_DLB   789
#define O_DLW   790
#define O_GUW   890
#define O_GUB   1090
#define O_CDUW  1100
#define O_GLW   1300
#define O_GLB   1500
#define O_CDLW  1510
#define SM2_F32 (SB + 1710)

__global__ __launch_bounds__(128, 4) void k2_post(
    const float* __restrict__ xh_u, const float* __restrict__ xh_l,
    const float* __restrict__ xf, const float* __restrict__ xp,
    const float* __restrict__ pdp_w1, const float* __restrict__ pdp_w2,
    const float* __restrict__ att_w, const float* __restrict__ att_b,
    const float* __restrict__ cU_aw, const float* __restrict__ cU_ab, const float* __restrict__ cU_w,
    const float* __restrict__ cL_aw, const float* __restrict__ cL_ab, const float* __restrict__ cL_w,
    const float* __restrict__ dU_aw, const float* __restrict__ dU_ab, const float* __restrict__ dU_w,
    const float* __restrict__ dL_aw, const float* __restrict__ dL_ab, const float* __restrict__ dL_w,
    const float* __restrict__ gU_w, const float* __restrict__ gU_b, const float* __restrict__ cdU_w,
    const float* __restrict__ gL_w, const float* __restrict__ gL_b, const float* __restrict__ cdL_w,
    float* __restrict__ out)
{
    __shared__ float sw[SM2_F32];           // 8.6 KB
    const int tid = threadIdx.x;

    for (int idx = tid; idx < 400; idx += 128) {
        int o = idx / 20, i = idx - o * 20;
        sw[idx] = pdp_w1[o * 276 + 256 + i];      // cat [h_fea, xh_u, xh_l]
    }
    if (tid < 20) {
        sw[400 + tid] = dU_aw[256 + tid];         // [h_fea, xf, xh_u]
        sw[420 + tid] = dL_aw[256 + tid];         // [h_fea, xf, xh_l]
    }
#define CPY(src, n_, off) for (int j = tid; j < (n_); j += 128) sw[SB + (off) + j] = (src)[j];
    CPY(pdp_w2, 200, O_W2)
    CPY(att_w, 20, O_ATTW)
    CPY(att_b, 2, O_ATTB)
    CPY(cU_aw, 40, O_CUAW)
    CPY(cU_ab, 4, O_CUAB)
    CPY(cU_w, 200, O_CUW)
    CPY(cL_aw, 20, O_CLAW)
    CPY(cL_ab, 2, O_CLAB)
    CPY(cL_w, 200, O_CLW)
    CPY(dU_ab, 1, O_DUB)
    CPY(dU_w, 100, O_DUW)
    CPY(dL_ab, 1, O_DLB)
    CPY(dL_w, 100, O_DLW)
    CPY(gU_w, 200, O_GUW)
    CPY(gU_b, 10, O_GUB)
    CPY(cdU_w, 200, O_CDUW)
    CPY(gL_w, 200, O_GLW)
    CPY(gL_b, 10, O_GLB)
    CPY(cdL_w, 200, O_CDLW)
#undef CPY
    __syncthreads();

    const int P  = blockIdx.x * 128 + tid;  // one pixel per thread
    const int n  = P >> 14;
    const int pp = P & (HW - 1);

    float acc[22];
#pragma unroll
    for (int o = 0; o < 22; o++) acc[o] = g_scratch[o * NPIX + P];

    const int base10 = n * 10 * HW + pp;
    float xu[10], xl[10], xfv[10];
#pragma unroll
    for (int i = 0; i < 10; i++) {
        xu[i]  = xh_u[base10 + i * HW];
        xl[i]  = xh_l[base10 + i * HW];
        xfv[i] = xf[base10 + i * HW];
    }

    // tails of the 276-channel dot products
#pragma unroll
    for (int o = 0; o < 20; o++) {
        float a = acc[o];
#pragma unroll
        for (int i = 0; i < 10; i++) {
            a = fmaf(xu[i], sw[o * 20 + i], a);
            a = fmaf(xl[i], sw[o * 20 + 10 + i], a);
        }
        acc[o] = a;
    }
    {
        float a = acc[20];
#pragma unroll
        for (int i = 0; i < 10; i++) {
            a = fmaf(xfv[i], sw[400 + i], a);
            a = fmaf(xu[i],  sw[410 + i], a);
        }
        acc[20] = a;
        float b = acc[21];
#pragma unroll
        for (int i = 0; i < 10; i++) {
            b = fmaf(xfv[i], sw[420 + i], b);
            b = fmaf(xl[i],  sw[430 + i], b);
        }
        acc[21] = b;
    }

    const float attu = sig1(acc[20] + sw[SB + O_DUB]);
    const float attl = sig1(acc[21] + sw[SB + O_DLB]);

#pragma unroll
    for (int o = 0; o < 20; o++) acc[o] = fmaxf(acc[o], 0.f);

    // dp grouped 10x10
    float dpu[10], dpl[10];
#pragma unroll
    for (int j = 0; j < 10; j++) {
        float s = 0.f, s2 = 0.f;
#pragma unroll
        for (int i = 0; i < 10; i++) {
            s  = fmaf(acc[i],      sw[SB + O_W2 + j * 10 + i], s);
            s2 = fmaf(acc[10 + i], sw[SB + O_W2 + 100 + j * 10 + i], s2);
        }
        dpu[j] = fmaxf(s, 0.f);
        dpl[j] = fmaxf(s2, 0.f);
    }

    // grouped gate attention
    float au = sw[SB + O_ATTB + 0], al = sw[SB + O_ATTB + 1];
#pragma unroll
    for (int i = 0; i < 10; i++) {
        au = fmaf(xu[i], sw[SB + O_ATTW + i], au);
        al = fmaf(xl[i], sw[SB + O_ATTW + 10 + i], al);
    }
    au = sig1(au);
    al = sig1(al);

    float m[10];

    // =================== U branch ===================
    {
        float msg0 = 0.f, msg1 = 0.f, msg2 = 0.f, msg3 = 0.f, msg4 = 0.f,
              msg5 = 0.f, msg6 = 0.f, msg7 = 0.f, msg8 = 0.f, msg9 = 0.f;
#pragma unroll
        for (int p = 0; p < 4; p++) {
            float ca = sw[SB + O_CUAB + p];
            float pv[10];
#pragma unroll
            for (int i = 0; i < 10; i++) {
                pv[i] = xp[((p * NB + n) * 10 + i) * HW + pp];
                ca = fmaf(pv[i], sw[SB + O_CUAW + p * 10 + i], ca);
            }
            ca = sig1(ca);
            msg0 = fmaf(pv[0], ca, msg0); msg1 = fmaf(pv[1], ca, msg1);
            msg2 = fmaf(pv[2], ca, msg2); msg3 = fmaf(pv[3], ca, msg3);
            msg4 = fmaf(pv[4], ca, msg4); msg5 = fmaf(pv[5], ca, msg5);
            msg6 = fmaf(pv[6], ca, msg6); msg7 = fmaf(pv[7], ca, msg7);
            msg8 = fmaf(pv[8], ca, msg8); msg9 = fmaf(pv[9], ca, msg9);
        }
        float msg[10] = {msg0, msg1, msg2, msg3, msg4, msg5, msg6, msg7, msg8, msg9};
#pragma unroll
        for (int j = 0; j < 10; j++) {
            float s = 0.f;
#pragma unroll
            for (int i = 0; i < 10; i++) s = fmaf(xu[i],  sw[SB + O_CUW + j * 20 + i], s);
#pragma unroll
            for (int i = 0; i < 10; i++) s = fmaf(msg[i], sw[SB + O_CUW + j * 20 + 10 + i], s);
            float xph = fmaxf(s, 0.f);
            float xlh = dpl[j] * al + xu[j] * au;
            float s3 = 0.f;
#pragma unroll
            for (int i = 0; i < 10; i++) s3 = fmaf(xfv[i], sw[SB + O_DUW + j * 10 + i], s3);
            float xfh = fmaxf(attu * s3, 0.f);
            m[j] = xph + xlh + xfh;
        }
#pragma unroll
        for (int j = 0; j < 10; j++) {
            float g = sw[SB + O_GUB + j], cd = 0.f;
#pragma unroll
            for (int i = 0; i < 10; i++) {
                g  = fmaf(xu[i], sw[SB + O_GUW + j * 20 + i], g);
                cd = fmaf(xu[i], sw[SB + O_CDUW + j * 20 + i], cd);
            }
#pragma unroll
            for (int i = 0; i < 10; i++) {
                g  = fmaf(m[i], sw[SB + O_GUW + j * 20 + 10 + i], g);
                cd = fmaf(m[i], sw[SB + O_CDUW + j * 20 + 10 + i], cd);
            }
            g = sig1(g);
            cd = fmaxf(cd, 0.f);
            out[(n * 10 + j) * HW + pp] = fmaf(g, cd - xu[j], xu[j]);
        }
        out[OUT_ATTU + n * HW + pp] = attu;
    }

    // =================== L branch ===================
    {
        float msg0 = 0.f, msg1 = 0.f, msg2 = 0.f, msg3 = 0.f, msg4 = 0.f,
              msg5 = 0.f, msg6 = 0.f, msg7 = 0.f, msg8 = 0.f, msg9 = 0.f;
#pragma unroll
        for (int p = 0; p < 2; p++) {
            float ca = sw[SB + O_CLAB + p];
            float pv[10];
#pragma unroll
            for (int i = 0; i < 10; i++) {
                pv[i] = xp[(((p + 4) * NB + n) * 10 + i) * HW + pp];
                ca = fmaf(pv[i], sw[SB + O_CLAW + p * 10 + i], ca);
            }
            ca = sig1(ca);
            msg0 = fmaf(pv[0], ca, msg0); msg1 = fmaf(pv[1], ca, msg1);
            msg2 = fmaf(pv[2], ca, msg2); msg3 = fmaf(pv[3], ca, msg3);
            msg4 = fmaf(pv[4], ca, msg4); msg5 = fmaf(pv[5], ca, msg5);
            msg6 = fmaf(pv[6], ca, msg6); msg7 = fmaf(pv[7], ca, msg7);
            msg8 = fmaf(pv[8], ca, msg8); msg9 = fmaf(pv[9], ca, msg9);
        }
        float msg[10] = {msg0, msg1, msg2, msg3, msg4, msg5, msg6, msg7, msg8, msg9};
#pragma unroll
        for (int j = 0; j < 10; j++) {
            float s = 0.f;
#pragma unroll
            for (int i = 0; i < 10; i++) s = fmaf(xl[i],  sw[SB + O_CLW + j * 20 + i], s);
#pragma unroll
            for (int i = 0; i < 10; i++) s = fmaf(msg[i], sw[SB + O_CLW + j * 20 + 10 + i], s);
            float xph = fmaxf(s, 0.f);
            float xuh = dpu[j] * au + xl[j] * al;
            float s3 = 0.f;
#pragma unroll
            for (int i = 0; i < 10; i++) s3 = fmaf(xfv[i], sw[SB + O_DLW + j * 10 + i], s3);
            float xfh = fmaxf(attl * s3, 0.f);
            m[j] = xph + xuh + xfh;
        }
#pragma unroll
        for (int j = 0; j < 10; j++) {
            float g = sw[SB + O_GLB + j], cd = 0.f;
#pragma unroll
            for (int i = 0; i < 10; i++) {
                g  = fmaf(xl[i], sw[SB + O_GLW + j * 20 + i], g);
                cd = fmaf(xl[i], sw[SB + O_CDLW + j * 20 + i], cd);
            }
#pragma unroll
            for (int i = 0; i < 10; i++) {
                g  = fmaf(m[i], sw[SB + O_GLW + j * 20 + 10 + i], g);
                cd = fmaf(m[i], sw[SB + O_CDLW + j * 20 + 10 + i], cd);
            }
            g = sig1(g);
            cd = fmaxf(cd, 0.f);
            out[OUT_XHL + (n * 10 + j) * HW + pp] = fmaf(g, cd - xl[j], xl[j]);
        }
        out[OUT_ATTL + n * HW + pp] = attl;
    }
}

extern "C" void kernel_launch(void* const* d_in, const int* in_sizes, int n_in,
                              void* d_out, int out_size)
{
    k1_main<<<1024, 256>>>(
        (const float*)d_in[0],   // h_fea
        (const float*)d_in[5],   // pdp_w1
        (const float*)d_in[15],  // decU_att_w
        (const float*)d_in[18]); // decL_att_w

    k2_post<<<1024, 128>>>(
        (const float*)d_in[1],  (const float*)d_in[2],
        (const float*)d_in[3],  (const float*)d_in[4],
        (const float*)d_in[5],  (const float*)d_in[6],
        (const float*)d_in[7],  (const float*)d_in[8],
        (const float*)d_in[9],  (const float*)d_in[10], (const float*)d_in[11],
        (const float*)d_in[12], (const float*)d_in[13], (const float*)d_in[14],
        (const float*)d_in[15], (const float*)d_in[16], (const float*)d_in[17],
        (const float*)d_in[18], (const float*)d_in[19], (const float*)d_in[20],
        (const float*)d_in[21], (const float*)d_in[22], (const float*)d_in[23],
        (const float*)d_in[24], (const float*)d_in[25], (const float*)d_in[26],
        (float*)d_out);
}

// round 13
// speedup vs baseline: 1.2544x; 1.2544x over previous
#include <cuda_runtime.h>

#define HW   16384      // 128*128
#define NCH  256
#define NB   8
#define NPIX 131072

typedef unsigned long long u64;

// ---------------- packed f32x2 helpers (sm_103a) ----------------
__device__ __forceinline__ u64 fma2(u64 a, u64 b, u64 c) {
    u64 d; asm("fma.rn.f32x2 %0,%1,%2,%3;" : "=l"(d) : "l"(a), "l"(b), "l"(c)); return d;
}
__device__ __forceinline__ u64 add2(u64 a, u64 b) {
    u64 d; asm("add.rn.f32x2 %0,%1,%2;" : "=l"(d) : "l"(a), "l"(b)); return d;
}
__device__ __forceinline__ u64 pk2(float x, float y) {
    u64 r; asm("mov.b64 %0,{%1,%2};" : "=l"(r) : "f"(x), "f"(y)); return r;
}
__device__ __forceinline__ float sig1(float x) {
    return __fdividef(1.f, 1.f + __expf(-x));
}

// 22 partial dot products, f32 layout [o][pixel]
__device__ float g_scratch[22 * NPIX];

// Output offsets (tuple flattened: xh_u_new, xh_l_new, att_u, att_l)
#define OUT_XHL  1310720
#define OUT_ATTU 2621440
#define OUT_ATTL 2752512

// =========================================================================
// Kernel 1: [131072 x 256] @ [256 x 22] streaming GEMM over h_fea.
// THIN THREADS: 1 pixel/thread, channel-split 2, 11 u64 pair-packed
// accumulators (22 regs). 2048 blocks x 128 thr -> ~28 warps/SM.
//  - weights in smem as pairs: swk[c*12 + o2] = (w_{2o2}, w_{2o2+1})
//  - pixel duplicated in reg: fma2((x,x),(w0,w1),acc) -> 2 outputs/instr
//  - channel halves combined via smem staging, coalesced transposed write
// =========================================================================
__global__ __launch_bounds__(128, 6) void k1_main(
    const float* __restrict__ h_fea,
    const float* __restrict__ pdp_w1,
    const float* __restrict__ dU_aw,
    const float* __restrict__ dL_aw)
{
    __shared__ u64 swk[3072];     // weights [c][12] pairs, 24576 B
    __shared__ u64 stag[704];     // staging [64 px][11], 5632 B
    const int tid = threadIdx.x;

    for (int idx = tid; idx < 3072; idx += 128) {
        int c = idx / 12, o2 = idx - c * 12;
        float lo = 0.f, hi = 0.f;
        if (o2 < 10) {
            lo = pdp_w1[(2 * o2) * 276 + c];
            hi = pdp_w1[(2 * o2 + 1) * 276 + c];
        } else if (o2 == 10) {
            lo = dU_aw[c];
            hi = dL_aw[c];
        }
        swk[idx] = pk2(lo, hi);
    }
    __syncthreads();

    const int g     = tid & 63;          // pixel within block (warp-contiguous)
    const int chalf = tid >> 6;          // 0: channels [0,128), 1: [128,256)
    const int ch0   = chalf * 128;
    const int Pb    = blockIdx.x * 64;   // 64 px per block
    const int P     = Pb + g;
    const int n     = P >> 14;           // 64 | 16384 -> no image straddle
    const int pp    = P & (HW - 1);
    const float* hb = h_fea + n * (NCH * HW) + ch0 * HW + pp;

    u64 acc[11];
#pragma unroll
    for (int o = 0; o < 11; o++) acc[o] = 0ull;

    float bA[4], bB[4];

#define LOAD_CHUNK(B, C0)                                                     \
    _Pragma("unroll")                                                         \
    for (int j = 0; j < 4; j++)                                               \
        B[j] = hb[((C0) + j) * HW];

#define COMP_CHUNK(B, C0)                                                     \
    _Pragma("unroll")                                                         \
    for (int j = 0; j < 4; j++) {                                             \
        u64 d = pk2(B[j], B[j]);                                              \
        const u64* wc = &swk[(ch0 + (C0) + j) * 12];                          \
        const ulonglong2* w2 = reinterpret_cast<const ulonglong2*>(wc);       \
        _Pragma("unroll")                                                     \
        for (int q = 0; q < 5; q++) {                                         \
            ulonglong2 wp = w2[q];                                            \
            acc[2 * q]     = fma2(d, wp.x, acc[2 * q]);                       \
            acc[2 * q + 1] = fma2(d, wp.y, acc[2 * q + 1]);                   \
        }                                                                     \
        acc[10] = fma2(d, wc[10], acc[10]);                                   \
    }

    LOAD_CHUNK(bA, 0)
#pragma unroll 1
    for (int c0 = 0; c0 < 128; c0 += 8) {
        LOAD_CHUNK(bB, c0 + 4)
        COMP_CHUNK(bA, c0)
        const int nxt = (c0 + 8) & 127;   // last iter reloads chunk 0 (dead)
        LOAD_CHUNK(bA, nxt)
        COMP_CHUNK(bB, c0 + 4)
    }
#undef LOAD_CHUNK
#undef COMP_CHUNK

    // ---- combine the two channel halves via staging ----
    if (chalf == 1) {
#pragma unroll
        for (int o2 = 0; o2 < 11; o2++)
            stag[g * 11 + o2] = acc[o2];
    }
    __syncthreads();
    if (chalf == 0) {
#pragma unroll
        for (int o2 = 0; o2 < 11; o2++)
            stag[g * 11 + o2] = add2(acc[o2], stag[g * 11 + o2]);
    }
    __syncthreads();

    // ---- coalesced transposed write: scratch f32 [o][P] ----
    // thread (o_half = tid>>6, j = tid&63): 11 outputs, 64-px rows
    const float* stf = reinterpret_cast<const float*>(stag);  // [px][22]
    const int j = tid & 63, oh = tid >> 6;
#pragma unroll
    for (int oo = 0; oo < 11; oo++) {
        int o = 2 * oo + oh;
        g_scratch[o * NPIX + Pb + j] = stf[j * 22 + o];
    }
}

// =========================================================================
// Kernel 2: tails + graph logic — SCALAR, 1 pixel/thread. (R4/R9-identical)
// =========================================================================
#define SB 440
#define O_W2    0
#define O_ATTW  200
#define O_ATTB  220
#define O_CUAW  222
#define O_CUAB  262
#define O_CUW   266
#define O_CLAW  466
#define O_CLAB  486
#define O_CLW   488
#define O_DUB   688
#define O_DUW   689
#define O_DLB   789
#define O_DLW   790
#define O_GUW   890
#define O_GUB   1090
#define O_CDUW  1100
#define O_GLW   1300
#define O_GLB   1500
#define O_CDLW  1510
#define SM2_F32 (SB + 1710)

__global__ __launch_bounds__(128, 4) void k2_post(
    const float* __restrict__ xh_u, const float* __restrict__ xh_l,
    const float* __restrict__ xf, const float* __restrict__ xp,
    const float* __restrict__ pdp_w1, const float* __restrict__ pdp_w2,
    const float* __restrict__ att_w, const float* __restrict__ att_b,
    const float* __restrict__ cU_aw, const float* __restrict__ cU_ab, const float* __restrict__ cU_w,
    const float* __restrict__ cL_aw, const float* __restrict__ cL_ab, const float* __restrict__ cL_w,
    const float* __restrict__ dU_aw, const float* __restrict__ dU_ab, const float* __restrict__ dU_w,
    const float* __restrict__ dL_aw, const float* __restrict__ dL_ab, const float* __restrict__ dL_w,
    const float* __restrict__ gU_w, const float* __restrict__ gU_b, const float* __restrict__ cdU_w,
    const float* __restrict__ gL_w, const float* __restrict__ gL_b, const float* __restrict__ cdL_w,
    float* __restrict__ out)
{
    __shared__ float sw[SM2_F32];           // 8.6 KB
    const int tid = threadIdx.x;

    for (int idx = tid; idx < 400; idx += 128) {
        int o = idx / 20, i = idx - o * 20;
        sw[idx] = pdp_w1[o * 276 + 256 + i];      // cat [h_fea, xh_u, xh_l]
    }
    if (tid < 20) {
        sw[400 + tid] = dU_aw[256 + tid];         // [h_fea, xf, xh_u]
        sw[420 + tid] = dL_aw[256 + tid];         // [h_fea, xf, xh_l]
    }
#define CPY(src, n_, off) for (int j = tid; j < (n_); j += 128) sw[SB + (off) + j] = (src)[j];
    CPY(pdp_w2, 200, O_W2)
    CPY(att_w, 20, O_ATTW)
    CPY(att_b, 2, O_ATTB)
    CPY(cU_aw, 40, O_CUAW)
    CPY(cU_ab, 4, O_CUAB)
    CPY(cU_w, 200, O_CUW)
    CPY(cL_aw, 20, O_CLAW)
    CPY(cL_ab, 2, O_CLAB)
    CPY(cL_w, 200, O_CLW)
    CPY(dU_ab, 1, O_DUB)
    CPY(dU_w, 100, O_DUW)
    CPY(dL_ab, 1, O_DLB)
    CPY(dL_w, 100, O_DLW)
    CPY(gU_w, 200, O_GUW)
    CPY(gU_b, 10, O_GUB)
    CPY(cdU_w, 200, O_CDUW)
    CPY(gL_w, 200, O_GLW)
    CPY(gL_b, 10, O_GLB)
    CPY(cdL_w, 200, O_CDLW)
#undef CPY
    __syncthreads();

    const int P  = blockIdx.x * 128 + tid;  // one pixel per thread
    const int n  = P >> 14;
    const int pp = P & (HW - 1);

    float acc[22];
#pragma unroll
    for (int o = 0; o < 22; o++) acc[o] = g_scratch[o * NPIX + P];

    const int base10 = n * 10 * HW + pp;
    float xu[10], xl[10], xfv[10];
#pragma unroll
    for (int i = 0; i < 10; i++) {
        xu[i]  = xh_u[base10 + i * HW];
        xl[i]  = xh_l[base10 + i * HW];
        xfv[i] = xf[base10 + i * HW];
    }

    // tails of the 276-channel dot products
#pragma unroll
    for (int o = 0; o < 20; o++) {
        float a = acc[o];
#pragma unroll
        for (int i = 0; i < 10; i++) {
            a = fmaf(xu[i], sw[o * 20 + i], a);
            a = fmaf(xl[i], sw[o * 20 + 10 + i], a);
        }
        acc[o] = a;
    }
    {
        float a = acc[20];
#pragma unroll
        for (int i = 0; i < 10; i++) {
            a = fmaf(xfv[i], sw[400 + i], a);
            a = fmaf(xu[i],  sw[410 + i], a);
        }
        acc[20] = a;
        float b = acc[21];
#pragma unroll
        for (int i = 0; i < 10; i++) {
            b = fmaf(xfv[i], sw[420 + i], b);
            b = fmaf(xl[i],  sw[430 + i], b);
        }
        acc[21] = b;
    }

    const float attu = sig1(acc[20] + sw[SB + O_DUB]);
    const float attl = sig1(acc[21] + sw[SB + O_DLB]);

#pragma unroll
    for (int o = 0; o < 20; o++) acc[o] = fmaxf(acc[o], 0.f);

    // dp grouped 10x10
    float dpu[10], dpl[10];
#pragma unroll
    for (int j = 0; j < 10; j++) {
        float s = 0.f, s2 = 0.f;
#pragma unroll
        for (int i = 0; i < 10; i++) {
            s  = fmaf(acc[i],      sw[SB + O_W2 + j * 10 + i], s);
            s2 = fmaf(acc[10 + i], sw[SB + O_W2 + 100 + j * 10 + i], s2);
        }
        dpu[j] = fmaxf(s, 0.f);
        dpl[j] = fmaxf(s2, 0.f);
    }

    // grouped gate attention
    float au = sw[SB + O_ATTB + 0], al = sw[SB + O_ATTB + 1];
#pragma unroll
    for (int i = 0; i < 10; i++) {
        au = fmaf(xu[i], sw[SB + O_ATTW + i], au);
        al = fmaf(xl[i], sw[SB + O_ATTW + 10 + i], al);
    }
    au = sig1(au);
    al = sig1(al);

    float m[10];

    // =================== U branch ===================
    {
        float msg0 = 0.f, msg1 = 0.f, msg2 = 0.f, msg3 = 0.f, msg4 = 0.f,
              msg5 = 0.f, msg6 = 0.f, msg7 = 0.f, msg8 = 0.f, msg9 = 0.f;
#pragma unroll
        for (int p = 0; p < 4; p++) {
            float ca = sw[SB + O_CUAB + p];
            float pv[10];
#pragma unroll
            for (int i = 0; i < 10; i++) {
                pv[i] = xp[((p * NB + n) * 10 + i) * HW + pp];
                ca = fmaf(pv[i], sw[SB + O_CUAW + p * 10 + i], ca);
            }
            ca = sig1(ca);
            msg0 = fmaf(pv[0], ca, msg0); msg1 = fmaf(pv[1], ca, msg1);
            msg2 = fmaf(pv[2], ca, msg2); msg3 = fmaf(pv[3], ca, msg3);
            msg4 = fmaf(pv[4], ca, msg4); msg5 = fmaf(pv[5], ca, msg5);
            msg6 = fmaf(pv[6], ca, msg6); msg7 = fmaf(pv[7], ca, msg7);
            msg8 = fmaf(pv[8], ca, msg8); msg9 = fmaf(pv[9], ca, msg9);
        }
        float msg[10] = {msg0, msg1, msg2, msg3, msg4, msg5, msg6, msg7, msg8, msg9};
#pragma unroll
        for (int j = 0; j < 10; j++) {
            float s = 0.f;
#pragma unroll
            for (int i = 0; i < 10; i++) s = fmaf(xu[i],  sw[SB + O_CUW + j * 20 + i], s);
#pragma unroll
            for (int i = 0; i < 10; i++) s = fmaf(msg[i], sw[SB + O_CUW + j * 20 + 10 + i], s);
            float xph = fmaxf(s, 0.f);
            float xlh = dpl[j] * al + xu[j] * au;
            float s3 = 0.f;
#pragma unroll
            for (int i = 0; i < 10; i++) s3 = fmaf(xfv[i], sw[SB + O_DUW + j * 10 + i], s3);
            float xfh = fmaxf(attu * s3, 0.f);
            m[j] = xph + xlh + xfh;
        }
#pragma unroll
        for (int j = 0; j < 10; j++) {
            float g = sw[SB + O_GUB + j], cd = 0.f;
#pragma unroll
            for (int i = 0; i < 10; i++) {
                g  = fmaf(xu[i], sw[SB + O_GUW + j * 20 + i], g);
                cd = fmaf(xu[i], sw[SB + O_CDUW + j * 20 + i], cd);
            }
#pragma unroll
            for (int i = 0; i < 10; i++) {
                g  = fmaf(m[i], sw[SB + O_GUW + j * 20 + 10 + i], g);
                cd = fmaf(m[i], sw[SB + O_CDUW + j * 20 + 10 + i], cd);
            }
            g = sig1(g);
            cd = fmaxf(cd, 0.f);
            out[(n * 10 + j) * HW + pp] = fmaf(g, cd - xu[j], xu[j]);
        }
        out[OUT_ATTU + n * HW + pp] = attu;
    }

    // =================== L branch ===================
    {
        float msg0 = 0.f, msg1 = 0.f, msg2 = 0.f, msg3 = 0.f, msg4 = 0.f,
              msg5 = 0.f, msg6 = 0.f, msg7 = 0.f, msg8 = 0.f, msg9 = 0.f;
#pragma unroll
        for (int p = 0; p < 2; p++) {
            float ca = sw[SB + O_CLAB + p];
            float pv[10];
#pragma unroll
            for (int i = 0; i < 10; i++) {
                pv[i] = xp[(((p + 4) * NB + n) * 10 + i) * HW + pp];
                ca = fmaf(pv[i], sw[SB + O_CLAW + p * 10 + i], ca);
            }
            ca = sig1(ca);
            msg0 = fmaf(pv[0], ca, msg0); msg1 = fmaf(pv[1], ca, msg1);
            msg2 = fmaf(pv[2], ca, msg2); msg3 = fmaf(pv[3], ca, msg3);
            msg4 = fmaf(pv[4], ca, msg4); msg5 = fmaf(pv[5], ca, msg5);
            msg6 = fmaf(pv[6], ca, msg6); msg7 = fmaf(pv[7], ca, msg7);
            msg8 = fmaf(pv[8], ca, msg8); msg9 = fmaf(pv[9], ca, msg9);
        }
        float msg[10] = {msg0, msg1, msg2, msg3, msg4, msg5, msg6, msg7, msg8, msg9};
#pragma unroll
        for (int j = 0; j < 10; j++) {
            float s = 0.f;
#pragma unroll
            for (int i = 0; i < 10; i++) s = fmaf(xl[i],  sw[SB + O_CLW + j * 20 + i], s);
#pragma unroll
            for (int i = 0; i < 10; i++) s = fmaf(msg[i], sw[SB + O_CLW + j * 20 + 10 + i], s);
            float xph = fmaxf(s, 0.f);
            float xuh = dpu[j] * au + xl[j] * al;
            float s3 = 0.f;
#pragma unroll
            for (int i = 0; i < 10; i++) s3 = fmaf(xfv[i], sw[SB + O_DLW + j * 10 + i], s3);
            float xfh = fmaxf(attl * s3, 0.f);
            m[j] = xph + xuh + xfh;
        }
#pragma unroll
        for (int j = 0; j < 10; j++) {
            float g = sw[SB + O_GLB + j], cd = 0.f;
#pragma unroll
            for (int i = 0; i < 10; i++) {
                g  = fmaf(xl[i], sw[SB + O_GLW + j * 20 + i], g);
                cd = fmaf(xl[i], sw[SB + O_CDLW + j * 20 + i], cd);
            }
#pragma unroll
            for (int i = 0; i < 10; i++) {
                g  = fmaf(m[i], sw[SB + O_GLW + j * 20 + 10 + i], g);
                cd = fmaf(m[i], sw[SB + O_CDLW + j * 20 + 10 + i], cd);
            }
            g = sig1(g);
            cd = fmaxf(cd, 0.f);
            out[OUT_XHL + (n * 10 + j) * HW + pp] = fmaf(g, cd - xl[j], xl[j]);
        }
        out[OUT_ATTL + n * HW + pp] = attl;
    }
}

extern "C" void kernel_launch(void* const* d_in, const int* in_sizes, int n_in,
                              void* d_out, int out_size)
{
    k1_main<<<2048, 128>>>(
        (const float*)d_in[0],   // h_fea
        (const float*)d_in[5],   // pdp_w1
        (const float*)d_in[15],  // decU_att_w
        (const float*)d_in[18]); // decL_att_w

    k2_post<<<1024, 128>>>(
        (const float*)d_in[1],  (const float*)d_in[2],
        (const float*)d_in[3],  (const float*)d_in[4],
        (const float*)d_in[5],  (const float*)d_in[6],
        (const float*)d_in[7],  (const float*)d_in[8],
        (const float*)d_in[9],  (const float*)d_in[10], (const float*)d_in[11],
        (const float*)d_in[12], (const float*)d_in[13], (const float*)d_in[14],
        (const float*)d_in[15], (const float*)d_in[16], (const float*)d_in[17],
        (const float*)d_in[18], (const float*)d_in[19], (const float*)d_in[20],
        (const float*)d_in[21], (const float*)d_in[22], (const float*)d_in[23],
        (const float*)d_in[24], (const float*)d_in[25], (const float*)d_in[26],
        (float*)d_out);
}